// round 10
// baseline (speedup 1.0000x reference)
#include <cuda_runtime.h>
#include <cuda_fp16.h>
#include <math.h>

#define BB     8192
#define MM     200
#define EE     64
#define NOTHER 128
#define H1     96
#define F1     128
#define F2     85
#define F3     64

// smem u32: W2 3328, hist 7488; floats: tgt 64, c 96, w2 96, aij 208, part 512,
//           x 256, h1 128, h2 88  -> total 12264 u32 = 49056 B (x4 CTAs = 196KB/SM)
#define SM1_U32  (3328 + 7488 + 64 + 96 + 96 + 208 + 512 + 256 + 128 + 88)
#define SM1_BYTES (SM1_U32 * 4)

__global__ __launch_bounds__(256, 4)
void din_fused(const float* __restrict__ hist, const float* __restrict__ target,
               const float* __restrict__ other,
               const float* __restrict__ aW1, const float* __restrict__ ab1,
               const float* __restrict__ aW2, const float* __restrict__ ab2,
               const float* __restrict__ oW1, const float* __restrict__ ob1,
               const float* __restrict__ oW2, const float* __restrict__ ob2,
               const float* __restrict__ oW3, const float* __restrict__ ob3,
               const float* __restrict__ fW,  const float* __restrict__ fb,
               float* __restrict__ out)
{
    extern __shared__ unsigned sm1[];
    unsigned* s_W2 = sm1;                 // half2 W1eff [k2*104 + n]
    unsigned* s_h  = sm1 + 3328;          // half2 hist  [row*36 + k2]
    float* s_tgt  = (float*)(sm1 + 3328 + 7488);
    float* s_c    = s_tgt + 64;
    float* s_w2   = s_c + 96;
    float* s_aij  = s_w2 + 96;
    float* s_part = s_aij + 208;          // [8][64]
    float* s_x    = s_part + 512;         // [256]
    float* s_h1   = s_x + 256;            // [128]
    float* s_h2   = s_h1 + 128;           // [88]

    const int b = blockIdx.x;
    const int t = threadIdx.x;
    const float* hb = hist + (size_t)b * MM * EE;

    if (t < EE) {
        const float tv = target[(size_t)b * EE + t];
        s_tgt[t] = tv;
        s_x[EE + t] = tv;                 // x[64..127] = target
    }
    if (t < H1) s_w2[t]  = aW2[t];
    if (t >= 128) {                       // x[128..255] = other (warps 4-7)
        s_x[128 + (t - 128)] = other[(size_t)b * NOTHER + (t - 128)];
    }
    __syncthreads();

    // ---- stage hist -> smem fp16 ----
    for (int idx = t; idx < MM * 16; idx += 256) {
        const int row = idx >> 4, q = idx & 15;
        float4 v = ((const float4*)(hb + (size_t)row * EE))[q];
        __half2 h01 = __floats2half2_rn(v.x, v.y);
        __half2 h23 = __floats2half2_rn(v.z, v.w);
        uint2 st;
        st.x = *(unsigned*)&h01;
        st.y = *(unsigned*)&h23;
        *(uint2*)(s_h + row * 36 + 2 * q) = st;
    }
    for (int idx = t; idx < 8 * 36; idx += 256)
        s_h[200 * 36 + idx] = 0u;

    // ---- W1eff build (half2) + c vector ----
    for (int idx = t; idx < 32 * H1; idx += 256) {
        const int k2 = idx / H1, n = idx - k2 * H1;
        const int e0 = 2 * k2, e1 = 2 * k2 + 1;
        float v0 = aW1[e0 * H1 + n] + s_tgt[e0] * aW1[(EE + e0) * H1 + n];
        float v1 = aW1[e1 * H1 + n] + s_tgt[e1] * aW1[(EE + e1) * H1 + n];
        __half2 p = __floats2half2_rn(v0, v1);
        s_W2[k2 * 104 + n] = *(unsigned*)&p;
    }
    if (t < H1) {
        float acc = ab1[t];
        #pragma unroll 8
        for (int e = 0; e < EE; e++)
            acc = fmaf(s_tgt[e], aW1[(2 * EE + e) * H1 + t], acc);
        s_c[t] = acc;
    }
    __syncthreads();

    const int warp = t >> 5, lane = t & 31;
    const int gid = lane >> 2, tig = lane & 3;
    const float bias2 = ab2[0];

    // ---- Phase 1: fp16 mma m16n8k16 ----
    for (int mt = warp; mt < 13; mt += 8) {
        unsigned A[4][4];
        const unsigned* hp = s_h + (mt * 16 + gid) * 36 + tig;
        #pragma unroll
        for (int ks = 0; ks < 4; ks++) {
            A[ks][0] = hp[8 * ks];
            A[ks][1] = hp[288 + 8 * ks];
            A[ks][2] = hp[8 * ks + 4];
            A[ks][3] = hp[288 + 8 * ks + 4];
        }

        float aij0 = 0.f, aij1 = 0.f;
        const unsigned* wb = s_W2 + tig * 104 + gid;

        #pragma unroll 1
        for (int nt = 0; nt < 12; nt++) {
            float c0 = 0.f, c1 = 0.f, c2 = 0.f, c3 = 0.f;
            #pragma unroll
            for (int ks = 0; ks < 4; ks++) {
                const unsigned b0 = wb[ks * 832 + nt * 8];
                const unsigned b1 = wb[ks * 832 + 416 + nt * 8];
                asm volatile(
                    "mma.sync.aligned.m16n8k16.row.col.f32.f16.f16.f32 "
                    "{%0,%1,%2,%3}, {%4,%5,%6,%7}, {%8,%9}, {%0,%1,%2,%3};"
                    : "+f"(c0), "+f"(c1), "+f"(c2), "+f"(c3)
                    : "r"(A[ks][0]), "r"(A[ks][1]), "r"(A[ks][2]), "r"(A[ks][3]),
                      "r"(b0), "r"(b1));
            }
            const int j0 = nt * 8 + 2 * tig;
            const float cc0 = s_c[j0],  cc1 = s_c[j0 + 1];
            const float w0  = s_w2[j0], w1  = s_w2[j0 + 1];
            aij0 = fmaf(fmaxf(c0 + cc0, 0.f), w0, aij0);
            aij0 = fmaf(fmaxf(c1 + cc1, 0.f), w1, aij0);
            aij1 = fmaf(fmaxf(c2 + cc0, 0.f), w0, aij1);
            aij1 = fmaf(fmaxf(c3 + cc1, 0.f), w1, aij1);
        }
        aij0 += __shfl_xor_sync(0xffffffffu, aij0, 1);
        aij0 += __shfl_xor_sync(0xffffffffu, aij0, 2);
        aij1 += __shfl_xor_sync(0xffffffffu, aij1, 1);
        aij1 += __shfl_xor_sync(0xffffffffu, aij1, 2);
        if (tig == 0) {
            const int r0 = mt * 16 + gid;
            if (r0 < MM)     s_aij[r0]     = aij0 + bias2;
            if (r0 + 8 < MM) s_aij[r0 + 8] = aij1 + bias2;
        }
    }
    __syncthreads();

    // ---- Phase 2: tmp[e] = sum_m aij[m]*hist[m][e] (fp16 smem, conflict-free) ----
    {
        const int e2 = lane;
        const int m0 = warp * 25;
        float acc0 = 0.f, acc1 = 0.f;
        #pragma unroll 5
        for (int m = m0; m < m0 + 25; m++) {
            const unsigned u = s_h[m * 36 + e2];
            const __half2 h = *(const __half2*)&u;
            const float2 f = __half22float2(h);
            const float a = s_aij[m];
            acc0 = fmaf(a, f.x, acc0);
            acc1 = fmaf(a, f.y, acc1);
        }
        float2 st; st.x = acc0; st.y = acc1;
        *(float2*)(s_part + warp * 64 + 2 * e2) = st;
    }
    __syncthreads();
    if (t < EE) {
        float v = 0.f;
        #pragma unroll
        for (int c = 0; c < 8; c++)
            v += s_part[c * 64 + t];
        s_x[t] = v;                       // x[0..63] = tmp
    }
    __syncthreads();

    // ---- MLP tail (fp32, weights L1/L2-hot, coalesced) ----
    if (t < F1) {
        float acc = ob1[t];
        #pragma unroll 8
        for (int k = 0; k < 256; k++)
            acc = fmaf(s_x[k], oW1[k * F1 + t], acc);
        s_h1[t] = fmaxf(acc, 0.f);
    }
    __syncthreads();
    if (t < F2) {
        float acc = ob2[t];
        #pragma unroll 8
        for (int k = 0; k < F1; k++)
            acc = fmaf(s_h1[k], oW2[k * F2 + t], acc);
        s_h2[t] = fmaxf(acc, 0.f);
    }
    __syncthreads();
    {
        float v = 0.f;
        if (t < F3) {
            float acc = ob3[t];
            #pragma unroll 5
            for (int k = 0; k < F2; k++)
                acc = fmaf(s_h2[k], oW3[k * F3 + t], acc);
            v = fmaxf(acc, 0.f) * fW[t];
        }
        if (t < 64) {
            #pragma unroll
            for (int off = 16; off; off >>= 1)
                v += __shfl_xor_sync(0xffffffffu, v, off);
            if (lane == 0) s_part[warp] = v;   // warps 0,1
        }
    }
    __syncthreads();
    if (t == 0)
        out[b] = 1.f / (1.f + expf(-(s_part[0] + s_part[1] + fb[0])));
}

extern "C" void kernel_launch(void* const* d_in, const int* in_sizes, int n_in,
                              void* d_out, int out_size)
{
    const float* hist   = (const float*)d_in[0];
    const float* target = (const float*)d_in[1];
    const float* other  = (const float*)d_in[2];
    const float* aW1    = (const float*)d_in[3];
    const float* ab1    = (const float*)d_in[4];
    const float* aW2    = (const float*)d_in[5];
    const float* ab2    = (const float*)d_in[6];
    const float* oW1    = (const float*)d_in[7];
    const float* ob1    = (const float*)d_in[8];
    const float* oW2    = (const float*)d_in[9];
    const float* ob2    = (const float*)d_in[10];
    const float* oW3    = (const float*)d_in[11];
    const float* ob3    = (const float*)d_in[12];
    const float* fW     = (const float*)d_in[13];
    const float* fb     = (const float*)d_in[14];
    float* out = (float*)d_out;

    static int configured = 0;
    if (!configured) {
        cudaFuncSetAttribute(din_fused, cudaFuncAttributeMaxDynamicSharedMemorySize,
                             SM1_BYTES);
        configured = 1;
    }
    din_fused<<<BB, 256, SM1_BYTES>>>(hist, target, other, aW1, ab1, aW2, ab2,
                                      oW1, ob1, oW2, ob2, oW3, ob3, fW, fb, out);
}